// round 1
// baseline (speedup 1.0000x reference)
#include <cuda_runtime.h>
#include <math.h>

#define IM_FE_RATIO 16.0f

// One block per (b, n) row. Warp 0 reduces the one-hot gather (mask, x, y);
// warp 1 stages the 5x5 gaussian kernel into shared; then 36 threads write the
// 6x6 blurred patch directly into the pre-zeroed output.
__global__ void inver_interp_patch_kernel(const float* __restrict__ Xg,
                                          const float* __restrict__ kp,
                                          const float* __restrict__ gk,
                                          float* __restrict__ out,
                                          int N, int H, int W) {
    const int row = blockIdx.x;          // 0 .. B*N-1
    const int b   = row / N;
    const int i   = row - b * N;
    const int t   = threadIdx.x;

    __shared__ float s_gk[25];
    __shared__ float s_red[3];           // mask, sum_x, sum_y

    // warp 1: stage gaussian kernel (depthwise filter is identical per channel;
    // first 25 floats of gk are the 5x5 kernel)
    if (t >= 32 && t < 32 + 25) s_gk[t - 32] = gk[t - 32];

    // warp 0: reduce one-hot gather over N (N <= 32 here)
    if (t < 32) {
        float xg = 0.f, kx = 0.f, ky = 0.f;
        if (t < N) {
            xg = Xg[((size_t)(b * N + i)) * N + t];
            const float* k2 = kp + ((size_t)(b * N + t)) * 2;
            kx = xg * k2[0];
            ky = xg * k2[1];
        }
        #pragma unroll
        for (int off = 16; off > 0; off >>= 1) {
            xg += __shfl_xor_sync(0xffffffffu, xg, off);
            kx += __shfl_xor_sync(0xffffffffu, kx, off);
            ky += __shfl_xor_sync(0xffffffffu, ky, off);
        }
        if (t == 0) { s_red[0] = xg; s_red[1] = kx; s_red[2] = ky; }
    }
    __syncthreads();

    const float mask = s_red[0];         // exactly 0.0f or 1.0f
    if (mask == 0.0f) return;            // row invalid -> output stays zero

    const float x = s_red[1] * (1.0f / IM_FE_RATIO) - 0.5f;
    const float y = s_red[2] * (1.0f / IM_FE_RATIO) - 0.5f;

    const float maxx = (float)(W - 1);
    const float maxy = (float)(H - 1);
    const float lox = fminf(fmaxf(floorf(x), 0.0f), maxx);
    const float hix = fminf(fmaxf(ceilf(x),  0.0f), maxx);
    const float loy = fminf(fmaxf(floorf(y), 0.0f), maxy);
    const float hiy = fminf(fmaxf(ceilf(y),  0.0f), maxy);

    const float upx = x - lox, lwx = 1.0f - upx;
    const float upy = y - loy, lwy = 1.0f - upy;

    const int x0 = (int)lox, x1 = (int)hix;
    const int y0 = (int)loy, y1 = (int)hiy;
    const int ox1 = x1 - x0;             // 0 or 1
    const int oy1 = y1 - y0;             // 0 or 1

    if (t < 36) {
        const int dy = t / 6;
        const int dx = t - dy * 6;
        const int py = y0 - 2 + dy;
        const int px = x0 - 2 + dx;
        if (py >= 0 && py < H && px >= 0 && px < W) {
            float val = 0.0f;
            // 4 corners: (oy, ox) in {0, oy1} x {0, ox1}, coefs wy*wx,
            // ordering matches the reference scatter-add (collisions sum).
            #pragma unroll
            for (int cy = 0; cy < 2; cy++) {
                const int   oy = cy ? oy1 : 0;
                const float wy = cy ? upy : lwy;
                const int   ki = dy - oy;
                if (ki < 0 || ki > 4) continue;
                #pragma unroll
                for (int cx = 0; cx < 2; cx++) {
                    const int   ox = cx ? ox1 : 0;
                    const float wx = cx ? upx : lwx;
                    const int   kj = dx - ox;
                    if (kj < 0 || kj > 4) continue;
                    val += (wy * wx) * s_gk[ki * 5 + kj];
                }
            }
            out[(size_t)row * H * W + (size_t)py * W + px] = val;
        }
    }
}

extern "C" void kernel_launch(void* const* d_in, const int* in_sizes, int n_in,
                              void* d_out, int out_size) {
    const float* Xg = (const float*)d_in[0];   // (B, N, N)
    const float* kp = (const float*)d_in[1];   // (B, N, 2)
    const float* gk = (const float*)d_in[2];   // (N, 1, 5, 5)

    const int rows = in_sizes[1] / 2;          // B*N
    const int N    = in_sizes[0] / rows;       // N (square one-hot)
    const int HW   = out_size / rows;          // H*W
    int W = (int)(sqrt((double)HW) + 0.5);
    int H = HW / W;

    // Bulk zero: output is ~all zeros; memset node is pure DRAM-write bound.
    cudaMemsetAsync(d_out, 0, (size_t)out_size * sizeof(float));

    // Scatter the 6x6 blurred patches on top.
    inver_interp_patch_kernel<<<rows, 64>>>(Xg, kp, gk, (float*)d_out, N, H, W);
}